// round 17
// baseline (speedup 1.0000x reference)
#include <cuda_runtime.h>
#include <cstddef>

#define NUSERS 200000
#define NITEMS 100000
#define DIM    64
#define NEDGES 3200000

// -------- scratch (no allocations allowed; __device__ globals are the sanctioned path) ----
__device__ __align__(256) float g_hu[(size_t)NUSERS * DIM];
__device__ __align__(256) float g_hi[(size_t)NITEMS * DIM];
__device__ __align__(256) float g_nu[(size_t)NUSERS * DIM];
__device__ __align__(256) float g_ni[(size_t)NITEMS * DIM];

// CSR scratch (rebuilt every call; no caching)
__device__ int  g_cnt_u[NUSERS];
__device__ int  g_rp_u[NUSERS + 1];
__device__ int  g_pos_u[NUSERS];
__device__ __align__(16) int2 g_edge_u[NEDGES];   // {src_item, w_bits}
__device__ int  g_cnt_i[NITEMS];
__device__ int  g_rp_i[NITEMS + 1];
__device__ int  g_pos_i[NITEMS];
__device__ __align__(16) int2 g_edge_i[NEDGES];   // {src_user, w_bits}
__device__ int  g_bsum_u[256];
__device__ int  g_bsum_i[256];

// ---------------------------------------------------------------------------
// Merged CSR build pieces
// ---------------------------------------------------------------------------
__global__ void hist2_kernel(const int* __restrict__ u_idx, const int* __restrict__ i_idx,
                             int* __restrict__ cnt_u, int* __restrict__ cnt_i, int n) {
    int e = blockIdx.x * blockDim.x + threadIdx.x;
    if (e >= n) return;
    atomicAdd(cnt_u + u_idx[e], 1);
    atomicAdd(cnt_i + i_idx[e], 1);
}

__global__ void scan_blocksum(const int* __restrict__ cnt, int* __restrict__ bsum, int n) {
    __shared__ int sh[1024];
    int i = blockIdx.x * 1024 + threadIdx.x;
    int v = (i < n) ? cnt[i] : 0;
    sh[threadIdx.x] = v;
    __syncthreads();
    for (int o = 512; o > 0; o >>= 1) {
        if (threadIdx.x < o) sh[threadIdx.x] += sh[threadIdx.x + o];
        __syncthreads();
    }
    if (threadIdx.x == 0) bsum[blockIdx.x] = sh[0];
}

__global__ void scan_bsums(int* __restrict__ bsum, int nb) {   // single block, 256 thr
    __shared__ int sh[256];
    int t = threadIdx.x;
    int v = (t < nb) ? bsum[t] : 0;
    sh[t] = v;
    __syncthreads();
    for (int o = 1; o < 256; o <<= 1) {
        int x = (t >= o) ? sh[t - o] : 0;
        __syncthreads();
        sh[t] += x;
        __syncthreads();
    }
    if (t < nb) bsum[t] = sh[t] - v;   // exclusive
}

__global__ void scan_write(const int* __restrict__ cnt, const int* __restrict__ bsum,
                           int* __restrict__ rowptr, int* __restrict__ pos, int n) {
    __shared__ int sh[1024];
    int t = threadIdx.x;
    int i = blockIdx.x * 1024 + t;
    int v = (i < n) ? cnt[i] : 0;
    sh[t] = v;
    __syncthreads();
    for (int o = 1; o < 1024; o <<= 1) {
        int x = (t >= o) ? sh[t - o] : 0;
        __syncthreads();
        sh[t] += x;
        __syncthreads();
    }
    if (i < n) {
        int start = bsum[blockIdx.x] + sh[t] - v;
        rowptr[i] = start;
        pos[i]    = start;
    }
    if (i == 0) rowptr[n] = NEDGES;
}

__global__ void scatter2_kernel(const int* __restrict__ u_idx, const int* __restrict__ i_idx,
                                const float* __restrict__ w_u2i, const float* __restrict__ w_i2u,
                                int* __restrict__ pos_u, int* __restrict__ pos_i,
                                int2* __restrict__ edge_u, int2* __restrict__ edge_i, int n) {
    int e = blockIdx.x * blockDim.x + threadIdx.x;
    if (e >= n) return;
    int u = u_idx[e], it = i_idx[e];
    int p = atomicAdd(pos_u + u, 1);
    edge_u[p] = make_int2(it, __float_as_int(w_u2i[e]));
    int q = atomicAdd(pos_i + it, 1);
    edge_i[q] = make_int2(u, __float_as_int(w_i2u[e]));
}

// ---------------------------------------------------------------------------
// Merged gather SpMM (user rows then item rows), warp per row.
// EXACT proven-742 inner loop (2-deep __ldg).
// ---------------------------------------------------------------------------
__global__ void __launch_bounds__(256) spmm_gather2(
    const int*   __restrict__ rp_u, const int2* __restrict__ edge_u,
    const float* __restrict__ src_u, float* __restrict__ out_u,
    const int*   __restrict__ rp_i, const int2* __restrict__ edge_i,
    const float* __restrict__ src_i, float* __restrict__ out_i)
{
    int wg   = (blockIdx.x * 256 + threadIdx.x) >> 5;
    int lane = threadIdx.x & 31;
    if (wg >= NUSERS + NITEMS) return;

    const int*   rowptr;
    const int2*  edges;
    const float* h;
    float*       out;
    int row;
    if (wg < NUSERS) {
        row = wg;           rowptr = rp_u; edges = edge_u; h = src_u; out = out_u;
    } else {
        row = wg - NUSERS;  rowptr = rp_i; edges = edge_i; h = src_i; out = out_i;
    }

    int start = __ldg(rowptr + row);
    int end   = __ldg(rowptr + row + 1);

    float2 acc = make_float2(0.f, 0.f);
    int j = start;
    for (; j + 1 < end; j += 2) {
        int2 e0 = __ldg(edges + j);
        int2 e1 = __ldg(edges + j + 1);
        float2 v0 = *reinterpret_cast<const float2*>(h + (size_t)e0.x * DIM + 2 * lane);
        float2 v1 = *reinterpret_cast<const float2*>(h + (size_t)e1.x * DIM + 2 * lane);
        float w0 = __int_as_float(e0.y);
        float w1 = __int_as_float(e1.y);
        acc.x = fmaf(w0, v0.x, acc.x);
        acc.y = fmaf(w0, v0.y, acc.y);
        acc.x = fmaf(w1, v1.x, acc.x);
        acc.y = fmaf(w1, v1.y, acc.y);
    }
    if (j < end) {
        int2 e0 = __ldg(edges + j);
        float2 v0 = *reinterpret_cast<const float2*>(h + (size_t)e0.x * DIM + 2 * lane);
        float w0 = __int_as_float(e0.y);
        acc.x = fmaf(w0, v0.x, acc.x);
        acc.y = fmaf(w0, v0.y, acc.y);
    }
    *reinterpret_cast<float2*>(out + (size_t)row * DIM + 2 * lane) = acc;
}

// ---------------------------------------------------------------------------
// Merged register-tiled dense+relu+L2norm, K split in 2 chunks of 64.
// X stored K-MAJOR in smem with 3-bit XOR swizzle on the 16B column group:
//   sXT[k][ (g ^ ((k>>2)&7))*4 + (m&3) ],  g = m>>2
// -> mainloop: 1 LDS.128 (x, 4 rows) + 2 LDS.128 (w) per k  (was 6 slots).
// smem: sXT 64*128 + sW 64*68 floats = 50.2 KB -> 4 blocks/SM.
// ---------------------------------------------------------------------------
#define SW_STRIDE 68
#define DN_SMEM ((64 * 128 + 64 * SW_STRIDE) * 4)

__global__ void __launch_bounds__(256, 4) dense_norm2(
    const float* __restrict__ hA, const float* __restrict__ neighA,
    const float* __restrict__ WA, float* __restrict__ outA, int blksA, int nrowsA,
    const float* __restrict__ hB, const float* __restrict__ neighB,
    const float* __restrict__ WB, float* __restrict__ outB, int nrowsB)
{
    extern __shared__ float smem[];
    float* sXT = smem;               // [64][128] swizzled k-major X
    float* sW  = smem + 64 * 128;    // [64][SW_STRIDE]

    const float *h, *neigh, *W;
    float* out;
    int row0, nrows;
    if ((int)blockIdx.x < blksA) {
        h = hA; neigh = neighA; W = WA; out = outA;
        row0 = blockIdx.x * 128; nrows = nrowsA;
    } else {
        h = hB; neigh = neighB; W = WB; out = outB;
        row0 = (blockIdx.x - blksA) * 128; nrows = nrowsB;
    }

    const int t  = threadIdx.x;
    const int tx = t & 7;
    const int ty = t >> 3;

    float acc[4][8];
    #pragma unroll
    for (int i = 0; i < 4; i++)
        #pragma unroll
        for (int j = 0; j < 8; j++) acc[i][j] = 0.f;

    #pragma unroll
    for (int c = 0; c < 2; c++) {
        const float* xsrc = (c == 0) ? h : neigh;
        if (c) __syncthreads();

        // ---- load X chunk transposed+swizzled
        #pragma unroll
        for (int i = 0; i < 8; i++) {
            int idx = t + i * 256;            // 0..2047
            int m   = idx >> 4;               // 0..127
            int kq  = idx & 15;               // float4 index within chunk
            int row = row0 + m;
            float4 v = make_float4(0.f, 0.f, 0.f, 0.f);
            if (row < nrows)
                v = *reinterpret_cast<const float4*>(xsrc + (size_t)row * DIM + 4 * kq);
            int gp = ((m >> 2) ^ (kq & 7)) * 4 + (m & 3);
            sXT[(4 * kq + 0) * 128 + gp] = v.x;
            sXT[(4 * kq + 1) * 128 + gp] = v.y;
            sXT[(4 * kq + 2) * 128 + gp] = v.z;
            sXT[(4 * kq + 3) * 128 + gp] = v.w;
        }
        // ---- load W chunk transposed: sW[kk][j] = W[j][c*64 + kk]
        #pragma unroll
        for (int i = 0; i < 4; i++) {
            int idx = t + i * 256;            // 0..1023
            int j   = idx >> 4;               // 0..63
            int kq  = idx & 15;
            float4 v = *reinterpret_cast<const float4*>(W + j * 128 + c * 64 + 4 * kq);
            sW[(4 * kq + 0) * SW_STRIDE + j] = v.x;
            sW[(4 * kq + 1) * SW_STRIDE + j] = v.y;
            sW[(4 * kq + 2) * SW_STRIDE + j] = v.z;
            sW[(4 * kq + 3) * SW_STRIDE + j] = v.w;
        }
        __syncthreads();

        const float* wb = sW + tx * 8;

        #pragma unroll 8
        for (int k = 0; k < 64; k++) {
            float4 xq = *reinterpret_cast<const float4*>(
                sXT + k * 128 + ((ty ^ ((k >> 2) & 7)) << 2));
            float4 w0 = *reinterpret_cast<const float4*>(wb + k * SW_STRIDE);
            float4 w1 = *reinterpret_cast<const float4*>(wb + k * SW_STRIDE + 4);
            #pragma unroll
            for (int i = 0; i < 4; i++) {
                float xi = (i == 0) ? xq.x : (i == 1) ? xq.y : (i == 2) ? xq.z : xq.w;
                acc[i][0] = fmaf(xi, w0.x, acc[i][0]);
                acc[i][1] = fmaf(xi, w0.y, acc[i][1]);
                acc[i][2] = fmaf(xi, w0.z, acc[i][2]);
                acc[i][3] = fmaf(xi, w0.w, acc[i][3]);
                acc[i][4] = fmaf(xi, w1.x, acc[i][4]);
                acc[i][5] = fmaf(xi, w1.y, acc[i][5]);
                acc[i][6] = fmaf(xi, w1.z, acc[i][6]);
                acc[i][7] = fmaf(xi, w1.w, acc[i][7]);
            }
        }
    }

    // ---- relu + row L2 norm (reduce over the 8-thread octet that owns a row)
    #pragma unroll
    for (int i = 0; i < 4; i++) {
        float ss = 0.f;
        #pragma unroll
        for (int j = 0; j < 8; j++) {
            float v = fmaxf(acc[i][j], 0.f);
            acc[i][j] = v;
            ss = fmaf(v, v, ss);
        }
        ss += __shfl_xor_sync(0xffffffffu, ss, 1);
        ss += __shfl_xor_sync(0xffffffffu, ss, 2);
        ss += __shfl_xor_sync(0xffffffffu, ss, 4);
        float s = 1.0f / fmaxf(sqrtf(ss), 1e-12f);

        int row = row0 + ty * 4 + i;
        if (row < nrows) {
            float* op = out + (size_t)row * DIM + tx * 8;
            *reinterpret_cast<float4*>(op) =
                make_float4(acc[i][0] * s, acc[i][1] * s, acc[i][2] * s, acc[i][3] * s);
            *reinterpret_cast<float4*>(op + 4) =
                make_float4(acc[i][4] * s, acc[i][5] * s, acc[i][6] * s, acc[i][7] * s);
        }
    }
}

// ---------------------------------------------------------------------------
extern "C" void kernel_launch(void* const* d_in, const int* in_sizes, int n_in,
                              void* d_out, int out_size)
{
    const float* user_emb = (const float*)d_in[0];
    const float* item_emb = (const float*)d_in[1];
    const float* Wu       = (const float*)d_in[2];   // [2][64][128]
    const float* Wi       = (const float*)d_in[3];
    const int*   u_idx    = (const int*)  d_in[4];
    const int*   i_idx    = (const int*)  d_in[5];
    const float* w_u2i    = (const float*)d_in[6];
    const float* w_i2u    = (const float*)d_in[7];

    float* out_u = (float*)d_out;
    float* out_i = out_u + (size_t)NUSERS * DIM;

    float *hu, *hi, *nu, *ni;
    int *cnt_u, *rp_u, *pos_u, *cnt_i, *rp_i, *pos_i, *bsum_u, *bsum_i;
    int2 *edge_u, *edge_i;
    cudaGetSymbolAddress((void**)&hu, g_hu);
    cudaGetSymbolAddress((void**)&hi, g_hi);
    cudaGetSymbolAddress((void**)&nu, g_nu);
    cudaGetSymbolAddress((void**)&ni, g_ni);
    cudaGetSymbolAddress((void**)&cnt_u, g_cnt_u);
    cudaGetSymbolAddress((void**)&rp_u,  g_rp_u);
    cudaGetSymbolAddress((void**)&pos_u, g_pos_u);
    cudaGetSymbolAddress((void**)&edge_u, g_edge_u);
    cudaGetSymbolAddress((void**)&cnt_i, g_cnt_i);
    cudaGetSymbolAddress((void**)&rp_i,  g_rp_i);
    cudaGetSymbolAddress((void**)&pos_i, g_pos_i);
    cudaGetSymbolAddress((void**)&edge_i, g_edge_i);
    cudaGetSymbolAddress((void**)&bsum_u, g_bsum_u);
    cudaGetSymbolAddress((void**)&bsum_i, g_bsum_i);

    static cudaStream_t s1 = nullptr;
    static cudaEvent_t evA = nullptr, evB = nullptr;
    if (!s1) {
        cudaFuncSetAttribute(dense_norm2,
                             cudaFuncAttributeMaxDynamicSharedMemorySize, DN_SMEM);
        cudaStreamCreateWithFlags(&s1, cudaStreamNonBlocking);
        cudaEventCreateWithFlags(&evA, cudaEventDisableTiming);
        cudaEventCreateWithFlags(&evB, cudaEventDisableTiming);
    }

    const int gather_blks  = ((NUSERS + NITEMS) * 32 + 255) / 256;   // 37500
    const int dense_u_blks = (NUSERS + 127) / 128;                    // 1563
    const int dense_i_blks = (NITEMS + 127) / 128;                    // 782
    const int dense_blks   = dense_u_blks + dense_i_blks;             // 2345

    cudaStream_t s0 = 0;

    // ---- merged histogram ----
    cudaMemsetAsync(cnt_u, 0, NUSERS * sizeof(int), s0);
    cudaMemsetAsync(cnt_i, 0, NITEMS * sizeof(int), s0);
    hist2_kernel<<<(NEDGES + 255) / 256, 256, 0, s0>>>(u_idx, i_idx, cnt_u, cnt_i, NEDGES);
    cudaEventRecord(evA, s0);
    cudaStreamWaitEvent(s1, evA, 0);

    // ---- the two scan chains in parallel (tiny kernels) ----
    {
        int nbu = (NUSERS + 1023) / 1024;
        scan_blocksum<<<nbu, 1024, 0, s0>>>(cnt_u, bsum_u, NUSERS);
        scan_bsums<<<1, 256, 0, s0>>>(bsum_u, nbu);
        scan_write<<<nbu, 1024, 0, s0>>>(cnt_u, bsum_u, rp_u, pos_u, NUSERS);

        int nbi = (NITEMS + 1023) / 1024;
        scan_blocksum<<<nbi, 1024, 0, s1>>>(cnt_i, bsum_i, NITEMS);
        scan_bsums<<<1, 256, 0, s1>>>(bsum_i, nbi);
        scan_write<<<nbi, 1024, 0, s1>>>(cnt_i, bsum_i, rp_i, pos_i, NITEMS);
        cudaEventRecord(evB, s1);
        cudaStreamWaitEvent(s0, evB, 0);
    }

    // ---- merged edge scatter (reads each input array once) ----
    scatter2_kernel<<<(NEDGES + 255) / 256, 256, 0, s0>>>(
        u_idx, i_idx, w_u2i, w_i2u, pos_u, pos_i, edge_u, edge_i, NEDGES);

    // ---------------- Layer 0 ----------------
    spmm_gather2<<<gather_blks, 256, 0, s0>>>(
        rp_u, edge_u, item_emb, nu,
        rp_i, edge_i, user_emb, ni);
    dense_norm2<<<dense_blks, 256, DN_SMEM, s0>>>(
        user_emb, nu, Wu,            hu, dense_u_blks, NUSERS,
        item_emb, ni, Wi,            hi, NITEMS);

    // ---------------- Layer 1 ----------------
    spmm_gather2<<<gather_blks, 256, 0, s0>>>(
        rp_u, edge_u, hi, nu,
        rp_i, edge_i, hu, ni);
    dense_norm2<<<dense_blks, 256, DN_SMEM, s0>>>(
        hu, nu, Wu + 64 * 128,       out_u, dense_u_blks, NUSERS,
        hi, ni, Wi + 64 * 128,       out_i, NITEMS);
}